// round 3
// baseline (speedup 1.0000x reference)
#include <cuda_runtime.h>
#include <cstdint>

// Problem constants
#define EMBED 1024
#define SEQ   16384   // 4 * 4096 tokens
#define HEADS 16
#define HDIM  64

// ---------------------------------------------------------------------------
// Scratch (allocation-free rule: __device__ globals)
// ---------------------------------------------------------------------------
__device__ float g_Xr[SEQ * EMBED];     // x rounded to tf32
__device__ float g_Wq[EMBED * EMBED];
__device__ float g_Wk[EMBED * EMBED];
__device__ float g_Wv[EMBED * EMBED];
__device__ float g_Wo[EMBED * EMBED];
__device__ float g_Q [SEQ * EMBED];
__device__ float g_K [SEQ * EMBED];
__device__ float g_V [SEQ * EMBED];
__device__ float g_AO[SEQ * EMBED];     // attention output, tf32-rounded

__device__ __forceinline__ float to_tf32(float x) {
    uint32_t u;
    asm("cvt.rna.tf32.f32 %0, %1;" : "=r"(u) : "f"(x));
    return __uint_as_float(u);
}

// ---------------------------------------------------------------------------
// Prep: round arrays to tf32 (removes all cvt from the GEMM hot loop;
// mma's internal truncation of pre-rounded values is then exact)
// ---------------------------------------------------------------------------
__global__ void round_tf32_k(const float4* __restrict__ src,
                             float4* __restrict__ dst, int n4) {
    int i = blockIdx.x * blockDim.x + threadIdx.x;
    if (i < n4) {
        float4 v = src[i];
        v.x = to_tf32(v.x); v.y = to_tf32(v.y);
        v.z = to_tf32(v.z); v.w = to_tf32(v.w);
        dst[i] = v;
    }
}

// ---------------------------------------------------------------------------
// TF32 tensor-core GEMM: C[M,N] = A[M,K] @ B[K,N] (+bias), all row-major fp32
// CTA tile 128x256, 8 warps of 64x64, BK=32, cp.async double buffer.
// ---------------------------------------------------------------------------
#define BM 128
#define BN 256
#define BK 32
#define AP 36    // A smem pitch (floats): bank = (4r+c)%32, 16B-aligned rows
#define BP 264   // B smem pitch (floats): bank = (8k+n)%32, 16B-aligned rows
#define ASZ (BM * AP)                 // 4608 floats / buffer
#define BSZ (BK * BP)                 // 8448 floats / buffer
#define GEMM_SMEM (2 * (ASZ + BSZ) * 4)  // 104448 bytes

__device__ __forceinline__ void cpa16(float* dst, const float* src) {
    uint32_t d = (uint32_t)__cvta_generic_to_shared(dst);
    asm volatile("cp.async.cg.shared.global [%0], [%1], 16;\n"
                 :: "r"(d), "l"(src));
}

__global__ void __launch_bounds__(256, 1)
gemm_tf32(const float* __restrict__ A, const float* __restrict__ B,
          float* __restrict__ C, const float* __restrict__ bias,
          int M, int N, int K)
{
    extern __shared__ float smem[];
    float* As = smem;
    float* Bs = smem + 2 * ASZ;

    const int tid  = threadIdx.x;
    const int lane = tid & 31;
    const int warp = tid >> 5;
    const int wm0  = (warp & 1) * 64;   // warp row offset in CTA tile
    const int wn0  = (warp >> 1) * 64;  // warp col offset
    const int m0   = blockIdx.x * BM;
    const int n0   = blockIdx.y * BN;

    float acc[4][8][4];
    #pragma unroll
    for (int i = 0; i < 4; i++)
        #pragma unroll
        for (int j = 0; j < 8; j++)
            #pragma unroll
            for (int r = 0; r < 4; r++) acc[i][j][r] = 0.f;

    auto load_tile = [&](int kt, int buf) {
        const int k0 = kt * BK;
        float* As_ = As + buf * ASZ;
        float* Bs_ = Bs + buf * BSZ;
        #pragma unroll
        for (int i = 0; i < 4; i++) {          // A: 128x32 = 1024 float4
            int idx = tid + i * 256;
            int r = idx >> 3, c = (idx & 7) * 4;
            cpa16(&As_[r * AP + c], &A[(m0 + r) * K + k0 + c]);
        }
        #pragma unroll
        for (int i = 0; i < 8; i++) {          // B: 32x256 = 2048 float4
            int idx = tid + i * 256;
            int r = idx >> 6, c = (idx & 63) * 4;
            cpa16(&Bs_[r * BP + c], &B[(k0 + r) * N + n0 + c]);
        }
        asm volatile("cp.async.commit_group;\n");
    };

    const int T = K / BK;
    load_tile(0, 0);
    int buf = 0;

    #pragma unroll 1
    for (int kt = 0; kt < T; ++kt) {
        if (kt + 1 < T) {
            load_tile(kt + 1, buf ^ 1);
            asm volatile("cp.async.wait_group 1;\n");
        } else {
            asm volatile("cp.async.wait_group 0;\n");
        }
        __syncthreads();

        const float* As_ = As + buf * ASZ;
        const float* Bs_ = Bs + buf * BSZ;

        #pragma unroll
        for (int kc = 0; kc < 4; ++kc) {       // 4 k-chunks of 8
            uint32_t a[4][4], b[8][2];
            #pragma unroll
            for (int mi = 0; mi < 4; ++mi) {
                int r = wm0 + mi * 16 + (lane >> 2);
                int c = kc * 8 + (lane & 3);
                a[mi][0] = __float_as_uint(As_[r * AP + c]);
                a[mi][1] = __float_as_uint(As_[(r + 8) * AP + c]);
                a[mi][2] = __float_as_uint(As_[r * AP + c + 4]);
                a[mi][3] = __float_as_uint(As_[(r + 8) * AP + c + 4]);
            }
            #pragma unroll
            for (int ni = 0; ni < 8; ++ni) {
                int kr = kc * 8 + (lane & 3);
                int nc = wn0 + ni * 8 + (lane >> 2);
                b[ni][0] = __float_as_uint(Bs_[kr * BP + nc]);
                b[ni][1] = __float_as_uint(Bs_[(kr + 4) * BP + nc]);
            }
            #pragma unroll
            for (int mi = 0; mi < 4; ++mi)
                #pragma unroll
                for (int ni = 0; ni < 8; ++ni)
                    asm volatile(
                        "mma.sync.aligned.m16n8k8.row.col.f32.tf32.tf32.f32 "
                        "{%0,%1,%2,%3}, {%4,%5,%6,%7}, {%8,%9}, {%0,%1,%2,%3};\n"
                        : "+f"(acc[mi][ni][0]), "+f"(acc[mi][ni][1]),
                          "+f"(acc[mi][ni][2]), "+f"(acc[mi][ni][3])
                        : "r"(a[mi][0]), "r"(a[mi][1]),
                          "r"(a[mi][2]), "r"(a[mi][3]),
                          "r"(b[ni][0]), "r"(b[ni][1]));
        }
        buf ^= 1;
        __syncthreads();   // all warps done reading before next prefetch overwrites
    }

    // Epilogue: float2 stores (c0,c1) and (c2,c3)
    #pragma unroll
    for (int mi = 0; mi < 4; ++mi) {
        #pragma unroll
        for (int ni = 0; ni < 8; ++ni) {
            int row = m0 + wm0 + mi * 16 + (lane >> 2);
            int col = n0 + wn0 + ni * 8 + 2 * (lane & 3);
            float o0 = acc[mi][ni][0], o1 = acc[mi][ni][1];
            float o2 = acc[mi][ni][2], o3 = acc[mi][ni][3];
            if (bias) {
                float b0 = bias[col], b1 = bias[col + 1];
                o0 += b0; o1 += b1; o2 += b0; o3 += b1;
            }
            *reinterpret_cast<float2*>(&C[row * N + col])       = make_float2(o0, o1);
            *reinterpret_cast<float2*>(&C[(row + 8) * N + col]) = make_float2(o2, o3);
        }
    }
}

// ---------------------------------------------------------------------------
// Cross-head attention: per token (16 heads x 64 dim),
// energy[hq,hk] = q[hq]·k[hk], softmax over hk, out = attn @ v.
// One 128-thread block per token. Head pitch 65 -> conflict-free smem.
// ---------------------------------------------------------------------------
#define HP 65
__global__ void attn_k(const float* __restrict__ Q, const float* __restrict__ K,
                       const float* __restrict__ V, float* __restrict__ O)
{
    __shared__ float sq[HEADS * HP], sk[HEADS * HP], sv[HEADS * HP];
    __shared__ float se[HEADS * HEADS], sa[HEADS * HEADS];
    const int t = threadIdx.x;
    const int base = blockIdx.x * EMBED;

    #pragma unroll
    for (int i = 0; i < 8; i++) {
        int idx = t + i * 128;
        int h = idx >> 6, d = idx & 63;
        sq[h * HP + d] = Q[base + idx];
        sk[h * HP + d] = K[base + idx];
        sv[h * HP + d] = V[base + idx];
    }
    __syncthreads();

    {   // energy: each thread computes 2 of the 256 entries
        int hq = t >> 3;
        int hk = (t & 7) * 2;
        float e0 = 0.f, e1 = 0.f;
        const float* qr = &sq[hq * HP];
        const float* k0 = &sk[hk * HP];
        const float* k1 = &sk[(hk + 1) * HP];
        #pragma unroll
        for (int d = 0; d < 64; ++d) {
            float qv = qr[d];
            e0 += qv * k0[d];
            e1 += qv * k1[d];
        }
        se[hq * HEADS + hk]     = e0 * 0.03125f;   // / sqrt(1024)
        se[hq * HEADS + hk + 1] = e1 * 0.03125f;
    }
    __syncthreads();

    if (t < HEADS) {   // softmax over hk, one thread per row
        float m = -1e30f;
        #pragma unroll
        for (int j = 0; j < HEADS; j++) m = fmaxf(m, se[t * HEADS + j]);
        float e[HEADS]; float s = 0.f;
        #pragma unroll
        for (int j = 0; j < HEADS; j++) { e[j] = __expf(se[t * HEADS + j] - m); s += e[j]; }
        float inv = 1.f / s;
        #pragma unroll
        for (int j = 0; j < HEADS; j++) sa[t * HEADS + j] = e[j] * inv;
    }
    __syncthreads();

    #pragma unroll
    for (int i = 0; i < 8; i++) {
        int idx = t + i * 128;
        int h = idx >> 6, d = idx & 63;
        float s = 0.f;
        #pragma unroll
        for (int hk = 0; hk < HEADS; ++hk)
            s += sa[h * HEADS + hk] * sv[hk * HP + d];
        O[base + idx] = to_tf32(s);   // pre-rounded for the final tf32 GEMM
    }
}

// ---------------------------------------------------------------------------
// Launch
// ---------------------------------------------------------------------------
extern "C" void kernel_launch(void* const* d_in, const int* in_sizes, int n_in,
                              void* d_out, int out_size)
{
    const float* x  = (const float*)d_in[0];
    const float* Wq = (const float*)d_in[1];
    const float* Wk = (const float*)d_in[2];
    const float* Wv = (const float*)d_in[3];
    const float* Wo = (const float*)d_in[4];
    const float* bo = (const float*)d_in[5];

    float *Xr, *Wqr, *Wkr, *Wvr, *Wor, *Q, *K, *V, *AO;
    cudaGetSymbolAddress((void**)&Xr,  g_Xr);
    cudaGetSymbolAddress((void**)&Wqr, g_Wq);
    cudaGetSymbolAddress((void**)&Wkr, g_Wk);
    cudaGetSymbolAddress((void**)&Wvr, g_Wv);
    cudaGetSymbolAddress((void**)&Wor, g_Wo);
    cudaGetSymbolAddress((void**)&Q,   g_Q);
    cudaGetSymbolAddress((void**)&K,   g_K);
    cudaGetSymbolAddress((void**)&V,   g_V);
    cudaGetSymbolAddress((void**)&AO,  g_AO);

    const int nx4 = SEQ * EMBED / 4;
    const int nw4 = EMBED * EMBED / 4;
    round_tf32_k<<<(nx4 + 255) / 256, 256>>>((const float4*)x,  (float4*)Xr,  nx4);
    round_tf32_k<<<(nw4 + 255) / 256, 256>>>((const float4*)Wq, (float4*)Wqr, nw4);
    round_tf32_k<<<(nw4 + 255) / 256, 256>>>((const float4*)Wk, (float4*)Wkr, nw4);
    round_tf32_k<<<(nw4 + 255) / 256, 256>>>((const float4*)Wv, (float4*)Wvr, nw4);
    round_tf32_k<<<(nw4 + 255) / 256, 256>>>((const float4*)Wo, (float4*)Wor, nw4);

    cudaFuncSetAttribute(gemm_tf32, cudaFuncAttributeMaxDynamicSharedMemorySize,
                         GEMM_SMEM);
    dim3 g(SEQ / BM, EMBED / BN);
    gemm_tf32<<<g, 256, GEMM_SMEM>>>(Xr, Wqr, Q, nullptr, SEQ, EMBED, EMBED);
    gemm_tf32<<<g, 256, GEMM_SMEM>>>(Xr, Wkr, K, nullptr, SEQ, EMBED, EMBED);
    gemm_tf32<<<g, 256, GEMM_SMEM>>>(Xr, Wvr, V, nullptr, SEQ, EMBED, EMBED);

    attn_k<<<SEQ, 128>>>(Q, K, V, AO);

    gemm_tf32<<<g, 256, GEMM_SMEM>>>(AO, Wor, (float*)d_out, bo, SEQ, EMBED, EMBED);
}

// round 6
// speedup vs baseline: 1.4458x; 1.4458x over previous
#include <cuda_runtime.h>
#include <cuda_fp16.h>
#include <cstdint>
#include <cstddef>

// Problem constants
#define EMBED 1024
#define SEQ   16384   // 4 * 4096 tokens
#define HEADS 16

// ---------------------------------------------------------------------------
// Scratch (allocation-free rule: __device__ globals)
// ---------------------------------------------------------------------------
__device__ __align__(1024) __half g_Xh [SEQ * EMBED];     // x -> fp16
__device__ __align__(1024) __half g_WqT[EMBED * EMBED];   // W^T fp16 [n][k]
__device__ __align__(1024) __half g_WkT[EMBED * EMBED];
__device__ __align__(1024) __half g_WvT[EMBED * EMBED];
__device__ __align__(1024) __half g_WoT[EMBED * EMBED];
__device__ __align__(1024) __half g_Qh [SEQ * EMBED];
__device__ __align__(1024) __half g_Kh [SEQ * EMBED];
__device__ __align__(1024) __half g_Vh [SEQ * EMBED];
__device__ __align__(1024) __half g_AOh[SEQ * EMBED];

__device__ __forceinline__ uint32_t h2_bits(__half2 h) {
    union { __half2 h; uint32_t u; } cvt;
    cvt.h = h;
    return cvt.u;
}

// ---------------------------------------------------------------------------
// Prep kernels
// ---------------------------------------------------------------------------
// 8 floats -> 8 halves per thread (16B store)
__global__ void f32_to_f16_k(const float4* __restrict__ src,
                             uint4* __restrict__ dst, int n8) {
    int i = blockIdx.x * blockDim.x + threadIdx.x;
    if (i < n8) {
        float4 v0 = src[2 * i], v1 = src[2 * i + 1];
        uint4 u;
        u.x = h2_bits(__floats2half2_rn(v0.x, v0.y));
        u.y = h2_bits(__floats2half2_rn(v0.z, v0.w));
        u.z = h2_bits(__floats2half2_rn(v1.x, v1.y));
        u.w = h2_bits(__floats2half2_rn(v1.z, v1.w));
        dst[i] = u;
    }
}

// dst[n][k] = fp16(src[k][n])   (1024x1024)
__global__ void transpose_f16_k(const float* __restrict__ src,
                                __half* __restrict__ dst) {
    __shared__ float t[32][33];
    const int tx = threadIdx.x, ty = threadIdx.y;
    const int n  = blockIdx.x * 32 + tx;
    const int k0 = blockIdx.y * 32;
    #pragma unroll
    for (int j = 0; j < 32; j += 8)
        t[ty + j][tx] = src[(size_t)(k0 + ty + j) * EMBED + n];
    __syncthreads();
    const int ok  = k0 + tx;
    const int on0 = blockIdx.x * 32;
    #pragma unroll
    for (int j = 0; j < 32; j += 8)
        dst[(size_t)(on0 + ty + j) * EMBED + ok] = __float2half_rn(t[tx][ty + j]);
}

// ---------------------------------------------------------------------------
// FP16 tensor-core GEMM: C[M,N] = A[M,K] @ B[N,K]^T
// A fp16 [M][K], Bw fp16 [N][K] (pre-transposed weights), accum fp32.
// CTA tile 128x256, 8 warps of 64x64, BK=32, 3-stage cp.async.
// Smem row pitch 80 B (40 halves): bank = (20*row + t) % 32 -> conflict-free.
// Output: fp16 (bias==null) or fp32 + bias.
// ---------------------------------------------------------------------------
#define BM 128
#define BN 256
#define BK 32
#define APITCH_B 80                    // bytes per smem row (64B data + pad)
#define A_BYTES (BM * APITCH_B)        // 10240
#define B_BYTES (BN * APITCH_B)        // 20480
#define STAGE   (A_BYTES + B_BYTES)    // 30720
#define NSTAGE  3
#define GEMM_SMEM (NSTAGE * STAGE)     // 92160

__device__ __forceinline__ void cpa16(void* dst, const void* src) {
    uint32_t d = (uint32_t)__cvta_generic_to_shared(dst);
    asm volatile("cp.async.cg.shared.global [%0], [%1], 16;\n"
                 :: "r"(d), "l"(src));
}

__device__ __forceinline__ void load_stage(char* sm, int s,
        const __half* __restrict__ A, const __half* __restrict__ Bw,
        int m0, int n0, int k0, int tid) {
    char* As = sm + s * STAGE;
    char* Bs = As + A_BYTES;
    const int row = tid >> 2;          // 0..63
    const int c   = (tid & 3) * 16;    // byte offset within 64B row data
    const int kh  = k0 + (tid & 3) * 8;  // half offset
    // A: 128 rows x 4 chunks = 512 cp, 2 per thread
    #pragma unroll
    for (int j = 0; j < 2; j++) {
        int r = row + j * 64;
        cpa16(As + r * APITCH_B + c, A + (size_t)(m0 + r) * EMBED + kh);
    }
    // B: 256 rows x 4 chunks = 1024 cp, 4 per thread
    #pragma unroll
    for (int j = 0; j < 4; j++) {
        int r = row + j * 64;
        cpa16(Bs + r * APITCH_B + c, Bw + (size_t)(n0 + r) * EMBED + kh);
    }
    asm volatile("cp.async.commit_group;\n" ::: "memory");
}

__global__ void __launch_bounds__(256, 1)
gemm_f16(const __half* __restrict__ A, const __half* __restrict__ Bw,
         void* __restrict__ Cv, const float* __restrict__ bias)
{
    extern __shared__ __align__(128) char smem[];
    const int tid  = threadIdx.x;
    const int lane = tid & 31;
    const int warp = tid >> 5;
    const int g    = lane >> 2;         // groupID 0..7
    const int t    = lane & 3;          // thread-in-group
    const int wm0  = (warp & 1) * 64;
    const int wn0  = (warp >> 1) * 64;
    const int m0   = blockIdx.x * BM;
    const int n0   = blockIdx.y * BN;

    float acc[4][8][4];
    #pragma unroll
    for (int i = 0; i < 4; i++)
        #pragma unroll
        for (int j = 0; j < 8; j++)
            #pragma unroll
            for (int r = 0; r < 4; r++) acc[i][j][r] = 0.f;

    const int T = EMBED / BK;   // 32
    load_stage(smem, 0, A, Bw, m0, n0, 0, tid);
    load_stage(smem, 1, A, Bw, m0, n0, BK, tid);

    #pragma unroll 1
    for (int kt = 0; kt < T; ++kt) {
        if (kt + 2 < T) {
            load_stage(smem, (kt + 2) % NSTAGE, A, Bw, m0, n0, (kt + 2) * BK, tid);
            asm volatile("cp.async.wait_group 2;\n" ::: "memory");
        } else if (kt + 1 < T) {
            asm volatile("cp.async.wait_group 1;\n" ::: "memory");
        } else {
            asm volatile("cp.async.wait_group 0;\n" ::: "memory");
        }
        __syncthreads();

        const char* As = smem + (kt % NSTAGE) * STAGE;
        const char* Bs = As + A_BYTES;

        #pragma unroll
        for (int kc = 0; kc < 2; ++kc) {           // two K=16 chunks
            uint32_t a[4][4], b[8][2];
            #pragma unroll
            for (int mi = 0; mi < 4; ++mi) {
                const char* p = As + (wm0 + mi * 16 + g) * APITCH_B
                                   + kc * 32 + t * 4;
                a[mi][0] = *(const uint32_t*)(p);
                a[mi][1] = *(const uint32_t*)(p + 8 * APITCH_B);
                a[mi][2] = *(const uint32_t*)(p + 16);
                a[mi][3] = *(const uint32_t*)(p + 8 * APITCH_B + 16);
            }
            #pragma unroll
            for (int ni = 0; ni < 8; ++ni) {
                const char* p = Bs + (wn0 + ni * 8 + g) * APITCH_B
                                   + kc * 32 + t * 4;
                b[ni][0] = *(const uint32_t*)(p);
                b[ni][1] = *(const uint32_t*)(p + 16);
            }
            #pragma unroll
            for (int mi = 0; mi < 4; ++mi)
                #pragma unroll
                for (int ni = 0; ni < 8; ++ni)
                    asm volatile(
                        "mma.sync.aligned.m16n8k16.row.col.f32.f16.f16.f32 "
                        "{%0,%1,%2,%3}, {%4,%5,%6,%7}, {%8,%9}, {%0,%1,%2,%3};\n"
                        : "+f"(acc[mi][ni][0]), "+f"(acc[mi][ni][1]),
                          "+f"(acc[mi][ni][2]), "+f"(acc[mi][ni][3])
                        : "r"(a[mi][0]), "r"(a[mi][1]),
                          "r"(a[mi][2]), "r"(a[mi][3]),
                          "r"(b[ni][0]), "r"(b[ni][1]));
        }
        __syncthreads();   // all warps done reading before stage reuse
    }

    // Epilogue
    if (bias) {            // fp32 output + bias (final projection)
        float* C = (float*)Cv;
        #pragma unroll
        for (int mi = 0; mi < 4; ++mi)
            #pragma unroll
            for (int ni = 0; ni < 8; ++ni) {
                int row = m0 + wm0 + mi * 16 + g;
                int col = n0 + wn0 + ni * 8 + 2 * t;
                float2 bb = *(const float2*)&bias[col];
                float2 o0 = make_float2(acc[mi][ni][0] + bb.x,
                                        acc[mi][ni][1] + bb.y);
                float2 o1 = make_float2(acc[mi][ni][2] + bb.x,
                                        acc[mi][ni][3] + bb.y);
                *(float2*)(C + (size_t)row * EMBED + col)       = o0;
                *(float2*)(C + (size_t)(row + 8) * EMBED + col) = o1;
            }
    } else {               // fp16 output (Q/K/V)
        __half* C = (__half*)Cv;
        #pragma unroll
        for (int mi = 0; mi < 4; ++mi)
            #pragma unroll
            for (int ni = 0; ni < 8; ++ni) {
                int row = m0 + wm0 + mi * 16 + g;
                int col = n0 + wn0 + ni * 8 + 2 * t;
                *(__half2*)(C + (size_t)row * EMBED + col) =
                    __floats2half2_rn(acc[mi][ni][0], acc[mi][ni][1]);
                *(__half2*)(C + (size_t)(row + 8) * EMBED + col) =
                    __floats2half2_rn(acc[mi][ni][2], acc[mi][ni][3]);
            }
    }
}

// ---------------------------------------------------------------------------
// Cross-head attention: per token 16x16 energy over heads, softmax, attn @ v.
// fp16 I/O, fp32 smem compute. One 128-thread block per token, head pitch 65.
// ---------------------------------------------------------------------------
#define HP 65
__global__ void attn_k(const __half2* __restrict__ Q2,
                       const __half2* __restrict__ K2,
                       const __half2* __restrict__ V2,
                       __half2* __restrict__ O2)
{
    __shared__ float sq[HEADS * HP], sk[HEADS * HP], sv[HEADS * HP];
    __shared__ float se[HEADS * HEADS], sa[HEADS * HEADS];
    const int t = threadIdx.x;
    const int base2 = blockIdx.x * (EMBED / 2);

    #pragma unroll
    for (int i = 0; i < 4; i++) {
        int idx2 = t + i * 128;            // half2 index within token
        int h = idx2 >> 5, d = (idx2 & 31) * 2;
        float2 q = __half22float2(Q2[base2 + idx2]);
        float2 k = __half22float2(K2[base2 + idx2]);
        float2 v = __half22float2(V2[base2 + idx2]);
        sq[h * HP + d] = q.x; sq[h * HP + d + 1] = q.y;
        sk[h * HP + d] = k.x; sk[h * HP + d + 1] = k.y;
        sv[h * HP + d] = v.x; sv[h * HP + d + 1] = v.y;
    }
    __syncthreads();

    {   // energy: each thread computes 2 of the 256 entries
        int hq = t >> 3;
        int hk = (t & 7) * 2;
        float e0 = 0.f, e1 = 0.f;
        const float* qr = &sq[hq * HP];
        const float* k0 = &sk[hk * HP];
        const float* k1 = &sk[(hk + 1) * HP];
        #pragma unroll
        for (int d = 0; d < 64; ++d) {
            float qv = qr[d];
            e0 += qv * k0[d];
            e1 += qv * k1[d];
        }
        se[hq * HEADS + hk]     = e0 * 0.03125f;   // / sqrt(1024)
        se[hq * HEADS + hk + 1] = e1 * 0.03125f;
    }
    __syncthreads();

    if (t < HEADS) {   // softmax over hk
        float m = -1e30f;
        #pragma unroll
        for (int j = 0; j < HEADS; j++) m = fmaxf(m, se[t * HEADS + j]);
        float e[HEADS]; float s = 0.f;
        #pragma unroll
        for (int j = 0; j < HEADS; j++) { e[j] = __expf(se[t * HEADS + j] - m); s += e[j]; }
        float inv = 1.f / s;
        #pragma unroll
        for (int j = 0; j < HEADS; j++) sa[t * HEADS + j] = e[j] * inv;
    }
    __syncthreads();

    #pragma unroll
    for (int i = 0; i < 4; i++) {
        int idx2 = t + i * 128;
        int h = idx2 >> 5, d = (idx2 & 31) * 2;
        float s0 = 0.f, s1 = 0.f;
        #pragma unroll
        for (int hk = 0; hk < HEADS; ++hk) {
            float a = sa[h * HEADS + hk];
            s0 += a * sv[hk * HP + d];
            s1 += a * sv[hk * HP + d + 1];
        }
        O2[base2 + idx2] = __floats2half2_rn(s0, s1);
    }
}

// ---------------------------------------------------------------------------
// Launch
// ---------------------------------------------------------------------------
extern "C" void kernel_launch(void* const* d_in, const int* in_sizes, int n_in,
                              void* d_out, int out_size)
{
    const float* x  = (const float*)d_in[0];
    const float* Wq = (const float*)d_in[1];
    const float* Wk = (const float*)d_in[2];
    const float* Wv = (const float*)d_in[3];
    const float* Wo = (const float*)d_in[4];
    const float* bo = (const float*)d_in[5];

    __half *Xh, *WqT, *WkT, *WvT, *WoT, *Qh, *Kh, *Vh, *AOh;
    cudaGetSymbolAddress((void**)&Xh,  g_Xh);
    cudaGetSymbolAddress((void**)&WqT, g_WqT);
    cudaGetSymbolAddress((void**)&WkT, g_WkT);
    cudaGetSymbolAddress((void**)&WvT, g_WvT);
    cudaGetSymbolAddress((void**)&WoT, g_WoT);
    cudaGetSymbolAddress((void**)&Qh,  g_Qh);
    cudaGetSymbolAddress((void**)&Kh,  g_Kh);
    cudaGetSymbolAddress((void**)&Vh,  g_Vh);
    cudaGetSymbolAddress((void**)&AOh, g_AOh);

    const int n8 = SEQ * EMBED / 8;
    f32_to_f16_k<<<(n8 + 255) / 256, 256>>>((const float4*)x, (uint4*)Xh, n8);

    dim3 tg(EMBED / 32, EMBED / 32), tb(32, 8);
    transpose_f16_k<<<tg, tb>>>(Wq, WqT);
    transpose_f16_k<<<tg, tb>>>(Wk, WkT);
    transpose_f16_k<<<tg, tb>>>(Wv, WvT);
    transpose_f16_k<<<tg, tb>>>(Wo, WoT);

    cudaFuncSetAttribute(gemm_f16, cudaFuncAttributeMaxDynamicSharedMemorySize,
                         GEMM_SMEM);
    dim3 g(SEQ / BM, EMBED / BN);   // (128, 4)
    gemm_f16<<<g, 256, GEMM_SMEM>>>(Xh, WqT, Qh, nullptr);
    gemm_f16<<<g, 256, GEMM_SMEM>>>(Xh, WkT, Kh, nullptr);
    gemm_f16<<<g, 256, GEMM_SMEM>>>(Xh, WvT, Vh, nullptr);

    attn_k<<<SEQ, 128>>>((const __half2*)Qh, (const __half2*)Kh,
                         (const __half2*)Vh, (__half2*)AOh);

    gemm_f16<<<g, 256, GEMM_SMEM>>>(AOh, WoT, d_out, bo);
}

// round 7
// speedup vs baseline: 1.6833x; 1.1643x over previous
#include <cuda_runtime.h>
#include <cuda_fp16.h>
#include <cstdint>
#include <cstddef>

// Problem constants
#define EMBED 1024
#define SEQ   16384   // 4 * 4096 tokens
#define HEADS 16

// ---------------------------------------------------------------------------
// Scratch (allocation-free rule: __device__ globals)
// ---------------------------------------------------------------------------
__device__ __align__(1024) __half g_Xh [SEQ * EMBED];         // x -> fp16
__device__ __align__(1024) __half g_WT [3 * EMBED * EMBED];   // [Wq;Wk;Wv]^T fp16 [n][k]
__device__ __align__(1024) __half g_WoT[EMBED * EMBED];       // Wo^T fp16 [n][k]
__device__ __align__(1024) __half g_Qh [SEQ * EMBED];
__device__ __align__(1024) __half g_Kh [SEQ * EMBED];
__device__ __align__(1024) __half g_Vh [SEQ * EMBED];
__device__ __align__(1024) __half g_AOh[SEQ * EMBED];

__device__ __forceinline__ uint32_t h2_bits(__half2 h) {
    union { __half2 h; uint32_t u; } cvt;
    cvt.h = h;
    return cvt.u;
}

// ---------------------------------------------------------------------------
// Prep kernels
// ---------------------------------------------------------------------------
__global__ void f32_to_f16_k(const float4* __restrict__ src,
                             uint4* __restrict__ dst, int n8) {
    int i = blockIdx.x * blockDim.x + threadIdx.x;
    if (i < n8) {
        float4 v0 = src[2 * i], v1 = src[2 * i + 1];
        uint4 u;
        u.x = h2_bits(__floats2half2_rn(v0.x, v0.y));
        u.y = h2_bits(__floats2half2_rn(v0.z, v0.w));
        u.z = h2_bits(__floats2half2_rn(v1.x, v1.y));
        u.w = h2_bits(__floats2half2_rn(v1.z, v1.w));
        dst[i] = u;
    }
}

// dst[n][k] = fp16(src[k][n])   (1024x1024)
__global__ void transpose_f16_k(const float* __restrict__ src,
                                __half* __restrict__ dst) {
    __shared__ float t[32][33];
    const int tx = threadIdx.x, ty = threadIdx.y;
    const int n  = blockIdx.x * 32 + tx;
    const int k0 = blockIdx.y * 32;
    #pragma unroll
    for (int j = 0; j < 32; j += 8)
        t[ty + j][tx] = src[(size_t)(k0 + ty + j) * EMBED + n];
    __syncthreads();
    const int ok  = k0 + tx;
    const int on0 = blockIdx.x * 32;
    #pragma unroll
    for (int j = 0; j < 32; j += 8)
        dst[(size_t)(on0 + ty + j) * EMBED + ok] = __float2half_rn(t[tx][ty + j]);
}

// ---------------------------------------------------------------------------
// FP16 tensor-core GEMM: C[M,N] = A[M,K] @ B[N,K]^T
// Tile 128x128, 8 warps (2M x 4N) of 64x32, BK=32, 3-stage cp.async, occ 2.
// Fragments via ldmatrix.m8n8.x4. Smem row pitch 80 B -> conflict-free.
// Fused-QKV mode: o0/o1/o2 fp16 outputs selected by blockIdx.y>>3.
// Final mode: of fp32 output + bias.
// ---------------------------------------------------------------------------
#define BM 128
#define BN 128
#define BK 32
#define PITCH 80                       // bytes per smem row (64B data + pad)
#define A_BYTES (BM * PITCH)           // 10240
#define B_BYTES (BN * PITCH)           // 10240
#define STAGE   (A_BYTES + B_BYTES)    // 20480
#define NSTAGE  3
#define GEMM_SMEM (NSTAGE * STAGE)     // 61440

__device__ __forceinline__ void cpa16(void* dst, const void* src) {
    uint32_t d = (uint32_t)__cvta_generic_to_shared(dst);
    asm volatile("cp.async.cg.shared.global [%0], [%1], 16;\n"
                 :: "r"(d), "l"(src));
}

__device__ __forceinline__ void ldsm4(uint32_t* r, uint32_t saddr) {
    asm volatile("ldmatrix.sync.aligned.m8n8.x4.shared.b16 {%0,%1,%2,%3}, [%4];"
                 : "=r"(r[0]), "=r"(r[1]), "=r"(r[2]), "=r"(r[3]) : "r"(saddr));
}

__device__ __forceinline__ void load_stage(char* sm, int s,
        const __half* __restrict__ A, const __half* __restrict__ Bw,
        int m0, int ngl0, int k0, int tid) {
    char* As = sm + s * STAGE;
    char* Bs = As + A_BYTES;
    const int row = tid >> 2;            // 0..63
    const int c   = (tid & 3) * 16;      // byte offset in 64B row data
    const int kh  = k0 + (tid & 3) * 8;  // half offset
    #pragma unroll
    for (int j = 0; j < 2; j++) {        // A: 128 rows
        int r = row + j * 64;
        cpa16(As + r * PITCH + c, A + (size_t)(m0 + r) * EMBED + kh);
    }
    #pragma unroll
    for (int j = 0; j < 2; j++) {        // B: 128 rows
        int r = row + j * 64;
        cpa16(Bs + r * PITCH + c, Bw + (size_t)(ngl0 + r) * EMBED + kh);
    }
    asm volatile("cp.async.commit_group;\n" ::: "memory");
}

__global__ void __launch_bounds__(256, 2)
gemm_f16(const __half* __restrict__ A, const __half* __restrict__ Bw,
         __half* __restrict__ o0, __half* __restrict__ o1,
         __half* __restrict__ o2,
         float* __restrict__ of, const float* __restrict__ bias)
{
    extern __shared__ __align__(128) char smem[];
    const uint32_t s0 = (uint32_t)__cvta_generic_to_shared(smem);
    const int tid  = threadIdx.x;
    const int lane = tid & 31;
    const int warp = tid >> 5;
    const int g    = lane >> 2;
    const int t    = lane & 3;
    const int wm0  = (warp & 1) * 64;    // warp tile 64x32
    const int wn0  = (warp >> 1) * 32;
    const int m0   = blockIdx.x * BM;
    const int ngl0 = blockIdx.y * BN;    // global B row (= output col) base

    // ldmatrix per-thread address components
    const int rA  = ((lane >> 3) & 1) * 8 + (lane & 7);
    const int kbA = (lane >> 4) * 16;
    const int rB  = ((lane >> 4) & 1) * 8 + (lane & 7);
    const int kbB = ((lane >> 3) & 1) * 16;
    const uint32_t aoff = (uint32_t)((wm0 + rA) * PITCH + kbA);
    const uint32_t boff = (uint32_t)((wn0 + rB) * PITCH + kbB) + A_BYTES;

    float acc[4][4][4];
    #pragma unroll
    for (int i = 0; i < 4; i++)
        #pragma unroll
        for (int j = 0; j < 4; j++)
            #pragma unroll
            for (int r = 0; r < 4; r++) acc[i][j][r] = 0.f;

    const int T = EMBED / BK;   // 32
    load_stage(smem, 0, A, Bw, m0, ngl0, 0, tid);
    load_stage(smem, 1, A, Bw, m0, ngl0, BK, tid);

    #pragma unroll 1
    for (int kt = 0; kt < T; ++kt) {
        if (kt + 2 < T) {
            load_stage(smem, (kt + 2) % NSTAGE, A, Bw, m0, ngl0, (kt + 2) * BK, tid);
            asm volatile("cp.async.wait_group 2;\n" ::: "memory");
        } else if (kt + 1 < T) {
            asm volatile("cp.async.wait_group 1;\n" ::: "memory");
        } else {
            asm volatile("cp.async.wait_group 0;\n" ::: "memory");
        }
        __syncthreads();

        const uint32_t su = s0 + (uint32_t)((kt % NSTAGE) * STAGE);

        #pragma unroll
        for (int kc = 0; kc < 2; ++kc) {           // two K=16 chunks
            uint32_t a[4][4], b[4][2];
            #pragma unroll
            for (int mi = 0; mi < 4; ++mi)
                ldsm4(a[mi], su + aoff + (uint32_t)(mi * 16 * PITCH + kc * 32));
            #pragma unroll
            for (int pi = 0; pi < 2; ++pi) {
                uint32_t r[4];
                ldsm4(r, su + boff + (uint32_t)(pi * 16 * PITCH + kc * 32));
                b[2 * pi][0]     = r[0]; b[2 * pi][1]     = r[1];
                b[2 * pi + 1][0] = r[2]; b[2 * pi + 1][1] = r[3];
            }
            #pragma unroll
            for (int mi = 0; mi < 4; ++mi)
                #pragma unroll
                for (int ni = 0; ni < 4; ++ni)
                    asm volatile(
                        "mma.sync.aligned.m16n8k16.row.col.f32.f16.f16.f32 "
                        "{%0,%1,%2,%3}, {%4,%5,%6,%7}, {%8,%9}, {%0,%1,%2,%3};\n"
                        : "+f"(acc[mi][ni][0]), "+f"(acc[mi][ni][1]),
                          "+f"(acc[mi][ni][2]), "+f"(acc[mi][ni][3])
                        : "r"(a[mi][0]), "r"(a[mi][1]),
                          "r"(a[mi][2]), "r"(a[mi][3]),
                          "r"(b[ni][0]), "r"(b[ni][1]));
        }
        __syncthreads();   // all warps done reading before stage reuse
    }

    // Epilogue
    if (of) {              // fp32 output + bias (final projection), N = EMBED
        #pragma unroll
        for (int mi = 0; mi < 4; ++mi)
            #pragma unroll
            for (int ni = 0; ni < 4; ++ni) {
                int row = m0 + wm0 + mi * 16 + g;
                int col = ngl0 + wn0 + ni * 8 + 2 * t;
                float2 bb = *(const float2*)&bias[col];
                *(float2*)(of + (size_t)row * EMBED + col) =
                    make_float2(acc[mi][ni][0] + bb.x, acc[mi][ni][1] + bb.y);
                *(float2*)(of + (size_t)(row + 8) * EMBED + col) =
                    make_float2(acc[mi][ni][2] + bb.x, acc[mi][ni][3] + bb.y);
            }
    } else {               // fused QKV: select output by blockIdx.y>>3
        int which = blockIdx.y >> 3;              // 1024 cols per output
        __half* C = (which == 0) ? o0 : (which == 1) ? o1 : o2;
        int cb = (blockIdx.y & 7) * BN;
        #pragma unroll
        for (int mi = 0; mi < 4; ++mi)
            #pragma unroll
            for (int ni = 0; ni < 4; ++ni) {
                int row = m0 + wm0 + mi * 16 + g;
                int col = cb + wn0 + ni * 8 + 2 * t;
                *(__half2*)(C + (size_t)row * EMBED + col) =
                    __floats2half2_rn(acc[mi][ni][0], acc[mi][ni][1]);
                *(__half2*)(C + (size_t)(row + 8) * EMBED + col) =
                    __floats2half2_rn(acc[mi][ni][2], acc[mi][ni][3]);
            }
    }
}

// ---------------------------------------------------------------------------
// Cross-head attention: per token 16x16 energy over heads, softmax, attn @ v.
// fp16 I/O, fp32 smem compute. One 128-thread block per token, head pitch 65.
// ---------------------------------------------------------------------------
#define HP 65
__global__ void attn_k(const __half2* __restrict__ Q2,
                       const __half2* __restrict__ K2,
                       const __half2* __restrict__ V2,
                       __half2* __restrict__ O2)
{
    __shared__ float sq[HEADS * HP], sk[HEADS * HP], sv[HEADS * HP];
    __shared__ float se[HEADS * HEADS], sa[HEADS * HEADS];
    const int t = threadIdx.x;
    const int base2 = blockIdx.x * (EMBED / 2);

    #pragma unroll
    for (int i = 0; i < 4; i++) {
        int idx2 = t + i * 128;
        int h = idx2 >> 5, d = (idx2 & 31) * 2;
        float2 q = __half22float2(Q2[base2 + idx2]);
        float2 k = __half22float2(K2[base2 + idx2]);
        float2 v = __half22float2(V2[base2 + idx2]);
        sq[h * HP + d] = q.x; sq[h * HP + d + 1] = q.y;
        sk[h * HP + d] = k.x; sk[h * HP + d + 1] = k.y;
        sv[h * HP + d] = v.x; sv[h * HP + d + 1] = v.y;
    }
    __syncthreads();

    {   // energy: each thread computes 2 of the 256 entries
        int hq = t >> 3;
        int hk = (t & 7) * 2;
        float e0 = 0.f, e1 = 0.f;
        const float* qr = &sq[hq * HP];
        const float* k0 = &sk[hk * HP];
        const float* k1 = &sk[(hk + 1) * HP];
        #pragma unroll
        for (int d = 0; d < 64; ++d) {
            float qv = qr[d];
            e0 += qv * k0[d];
            e1 += qv * k1[d];
        }
        se[hq * HEADS + hk]     = e0 * 0.03125f;   // / sqrt(1024)
        se[hq * HEADS + hk + 1] = e1 * 0.03125f;
    }
    __syncthreads();

    if (t < HEADS) {
        float m = -1e30f;
        #pragma unroll
        for (int j = 0; j < HEADS; j++) m = fmaxf(m, se[t * HEADS + j]);
        float e[HEADS]; float s = 0.f;
        #pragma unroll
        for (int j = 0; j < HEADS; j++) { e[j] = __expf(se[t * HEADS + j] - m); s += e[j]; }
        float inv = 1.f / s;
        #pragma unroll
        for (int j = 0; j < HEADS; j++) sa[t * HEADS + j] = e[j] * inv;
    }
    __syncthreads();

    #pragma unroll
    for (int i = 0; i < 4; i++) {
        int idx2 = t + i * 128;
        int h = idx2 >> 5, d = (idx2 & 31) * 2;
        float s0 = 0.f, s1 = 0.f;
        #pragma unroll
        for (int hk = 0; hk < HEADS; ++hk) {
            float a = sa[h * HEADS + hk];
            s0 += a * sv[hk * HP + d];
            s1 += a * sv[hk * HP + d + 1];
        }
        O2[base2 + idx2] = __floats2half2_rn(s0, s1);
    }
}

// ---------------------------------------------------------------------------
// Launch
// ---------------------------------------------------------------------------
extern "C" void kernel_launch(void* const* d_in, const int* in_sizes, int n_in,
                              void* d_out, int out_size)
{
    const float* x  = (const float*)d_in[0];
    const float* Wq = (const float*)d_in[1];
    const float* Wk = (const float*)d_in[2];
    const float* Wv = (const float*)d_in[3];
    const float* Wo = (const float*)d_in[4];
    const float* bo = (const float*)d_in[5];

    __half *Xh, *WT, *WoT, *Qh, *Kh, *Vh, *AOh;
    cudaGetSymbolAddress((void**)&Xh,  g_Xh);
    cudaGetSymbolAddress((void**)&WT,  g_WT);
    cudaGetSymbolAddress((void**)&WoT, g_WoT);
    cudaGetSymbolAddress((void**)&Qh,  g_Qh);
    cudaGetSymbolAddress((void**)&Kh,  g_Kh);
    cudaGetSymbolAddress((void**)&Vh,  g_Vh);
    cudaGetSymbolAddress((void**)&AOh, g_AOh);

    const int n8 = SEQ * EMBED / 8;
    f32_to_f16_k<<<(n8 + 255) / 256, 256>>>((const float4*)x, (uint4*)Xh, n8);

    dim3 tg(EMBED / 32, EMBED / 32), tb(32, 8);
    transpose_f16_k<<<tg, tb>>>(Wq, WT);
    transpose_f16_k<<<tg, tb>>>(Wk, WT + (size_t)EMBED * EMBED);
    transpose_f16_k<<<tg, tb>>>(Wv, WT + (size_t)2 * EMBED * EMBED);
    transpose_f16_k<<<tg, tb>>>(Wo, WoT);

    cudaFuncSetAttribute(gemm_f16, cudaFuncAttributeMaxDynamicSharedMemorySize,
                         GEMM_SMEM);
    // Fused QKV: N = 3072
    dim3 gqkv(SEQ / BM, 3 * EMBED / BN);   // (128, 24)
    gemm_f16<<<gqkv, 256, GEMM_SMEM>>>(Xh, WT, Qh, Kh, Vh, nullptr, nullptr);

    attn_k<<<SEQ, 128>>>((const __half2*)Qh, (const __half2*)Kh,
                         (const __half2*)Vh, (__half2*)AOh);

    // Final projection: N = 1024, fp32 out + bias
    dim3 go(SEQ / BM, EMBED / BN);         // (128, 8)
    gemm_f16<<<go, 256, GEMM_SMEM>>>(AOh, WoT, nullptr, nullptr, nullptr,
                                     (float*)d_out, bo);
}